// round 15
// baseline (speedup 1.0000x reference)
#include <cuda_runtime.h>

// ADSTFT: adaptive-window STFT, B=4, L=80000, N=512, F=257, STRIDE=256, T=311
// Outputs (concatenated into float* d_out):
//   [0, B*F*T)        spec[b][f][t] = |stft| + eps
//   [B*F*T, 2*B*F*T)  stft real plane, (b,f,t) order     } PLANAR layout
//   [2*B*F*T, 3*B*F*T) stft imag plane, (b,f,t) order    } (R13: interleaved
//   falsified for BOTH im signs: 1.410664 / 1.410343 — real parts identical
//   in those runs, so the mismatch is positional, not sign.)
//
// Radix-2 fold: S[f] = sum_{n<256} (g[n] + (-1)^f g[n+256]) e^{-2pi i f n/512}
// R12 fix (validated R13): HSTRIDE 520 — out0 restored to 8.56e-6.

#define Bc 4
#define Lc 80000
#define Nc 512
#define Fc 257
#define Tc 311
#define TT 8
#define THREADS 288
#define HODD 260      // odd-f region offset within h_sm row (16B aligned, bank-offset 4)
#define HSTRIDE 520   // row stride: HODD + 256 = 516, padded to 520 (16B-divisible)
#define BFT (Bc * Fc * Tc)

__global__ __launch_bounds__(THREADS) void adstft_kernel(
    const float* __restrict__ x,
    const float* __restrict__ win_length,
    const float* __restrict__ strides,
    float* __restrict__ out)
{
    __shared__ float  g_sm[TT][Nc];       // windowed frames
    __shared__ float  h_sm[TT][HSTRIDE];  // folded: [0..255] even-f, [260..515] odd-f
    __shared__ float2 tab[Nc];            // exp(-2*pi*i*k/512)
    __shared__ float  frac_sm[TT];

    const int tid = threadIdx.x;
    const int t0  = blockIdx.x * TT;
    const int b   = blockIdx.y;

    // runtime params (clipped as in reference)
    float wl = win_length[0];
    wl = fminf(fmaxf(wl, 25.6f), 512.0f);          // WIN_MIN = N/20, WIN_MAX = N
    float st = strides[0];
    st = fminf(fmaxf(st, 0.0f), 512.0f);           // STRIDE_MIN=0, STRIDE_MAX=max(N,STRIDE)

    const float hi      = ceilf((511.0f + wl) * 0.5f);   // ceil((N-1+wl)/2)
    const float lo      = floorf((511.0f - wl) * 0.5f);  // floor((N-1-wl)/2)
    const float coff    = (wl - 511.0f) * 0.5f;          // (wl - N + 1)/2
    const float inv_wl2 = 2.0f / wl;                     // cos(2*pi*y/wl) = cospif(2y/wl)

    // Twiddle table: tab[k] = exp(-2*pi*i*k/512)
    for (int k = tid; k < Nc; k += THREADS) {
        float s, c;
        sincospif((float)k * (1.0f / 256.0f), &s, &c);
        tab[k] = make_float2(c, -s);
    }

    // Windowed frames g[tt][n] = x[b, floor(st*t)+n] * tap(n - frac) / 256
    for (int tt = 0; tt < TT; ++tt) {
        const int t = t0 + tt;
        const float frames = st * (float)t;          // frames[t] = t * st
        const float fl     = floorf(frames);
        const float frac   = frames - fl;
        const int   i0     = (int)fl;
        if (tid == 0) frac_sm[tt] = frac;
        const bool tv = (t < Tc);
        for (int n = tid; n < Nc; n += THREADS) {
            float val = 0.0f;
            if (tv) {
                const float base = (float)n - frac;
                if (base > lo && base < hi) {        // zero if base<=lo or base>=hi
                    const float tap = 0.5f - 0.5f * cospif((base + coff) * inv_wl2);
                    const int i = i0 + n;
                    if (i >= 0 && i < Lc) {
                        val = x[b * Lc + i] * tap * (1.0f / 256.0f);  // tap / N * 2
                    }
                }
            }
            g_sm[tt][n] = val;
        }
    }
    __syncthreads();

    // Radix-2 fold: h_even[n] = g[n]+g[n+256], h_odd[n] = g[n]-g[n+256]
    for (int idx = tid; idx < TT * 256; idx += THREADS) {
        const int tt = idx >> 8;
        const int n  = idx & 255;
        const float a = g_sm[tt][n];
        const float c = g_sm[tt][n + 256];
        h_sm[tt][n]        = a + c;
        h_sm[tt][HODD + n] = a - c;
    }
    __syncthreads();

    const int f = tid;
    if (f >= Fc) return;   // 257 active lanes; no further barriers below

    const int po = (f & 1) ? HODD : 0;   // parity-selected folded region

    float re[TT], im[TT];
#pragma unroll
    for (int tt = 0; tt < TT; ++tt) { re[tt] = 0.0f; im[tt] = 0.0f; }

    // Folded DFT: 256 iterations. h loaded as broadcast LDS.128 (two disjoint
    // broadcast groups by parity); twiddles walk k = (k+f) mod 512.
    int k = 0;
    for (int n = 0; n < 256; n += 4) {
        const float2 w0 = tab[k]; k = (k + f) & (Nc - 1);
        const float2 w1 = tab[k]; k = (k + f) & (Nc - 1);
        const float2 w2 = tab[k]; k = (k + f) & (Nc - 1);
        const float2 w3 = tab[k]; k = (k + f) & (Nc - 1);
#pragma unroll
        for (int tt = 0; tt < TT; ++tt) {
            const float4 g = *(const float4*)&h_sm[tt][po + n];
            re[tt] = fmaf(g.x, w0.x, re[tt]); im[tt] = fmaf(g.x, w0.y, im[tt]);
            re[tt] = fmaf(g.y, w1.x, re[tt]); im[tt] = fmaf(g.y, w1.y, im[tt]);
            re[tt] = fmaf(g.z, w2.x, re[tt]); im[tt] = fmaf(g.z, w2.y, im[tt]);
            re[tt] = fmaf(g.w, w3.x, re[tt]); im[tt] = fmaf(g.w, w3.y, im[tt]);
        }
    }

    // Fractional shift + magnitude + store (PLANAR complex layout)
#pragma unroll
    for (int tt = 0; tt < TT; ++tt) {
        const int t = t0 + tt;
        if (t >= Tc) break;
        const float ang = frac_sm[tt] * (float)f * (1.0f / 256.0f);  // shift = exp(+i*pi*ang)
        float ss, cc;
        sincospif(ang, &ss, &cc);
        const float r2 = re[tt] * cc - im[tt] * ss;
        const float i2 = re[tt] * ss + im[tt] * cc;
        const float spec = sqrtf(r2 * r2 + i2 * i2) + 1.1920928955078125e-7f;
        const int o1 = (b * Fc + f) * Tc + t;
        out[o1]           = spec;
        out[BFT + o1]     = r2;   // real plane
        out[2 * BFT + o1] = i2;   // imag plane
    }
}

extern "C" void kernel_launch(void* const* d_in, const int* in_sizes, int n_in,
                              void* d_out, int out_size) {
    const float* x  = (const float*)d_in[0];
    const float* wl = (const float*)d_in[1];
    const float* st = (const float*)d_in[2];
    dim3 grid((Tc + TT - 1) / TT, Bc);
    adstft_kernel<<<grid, THREADS>>>(x, wl, st, (float*)d_out);
}

// round 16
// speedup vs baseline: 1.4129x; 1.4129x over previous
#include <cuda_runtime.h>

// ADSTFT: adaptive-window STFT, B=4, L=80000, N=512, F=257, STRIDE=256, T=311
// Outputs (PLANAR, validated R15 @35.8us):
//   [0, BFT)       spec[b][f][t] = |stft| + eps
//   [BFT, 2*BFT)   stft real plane, (b,f,t)
//   [2*BFT, 3*BFT) stft imag plane, (b,f,t)
//
// R15 ncu: LDS-conflict-bound (twiddle table stride-f loads ~6-way mean
// conflict), occ 13.5%, 2-wave tail. R16: twiddle recurrence (4 chains
// stepped by w^4), TT=4 (grid 312), fold fused into window phase
// (smem 8.4KB -> 4+ CTAs/SM).

#define Bc 4
#define Lc 80000
#define Nc 512
#define Fc 257
#define Tc 311
#define TT 4
#define THREADS 288
#define HODD 260      // odd-f region offset in h row (16B aligned, bank offset 4)
#define HSTRIDE 520   // HODD + 256 = 516 -> pad to 520 (16B-divisible)
#define BFT (Bc * Fc * Tc)

__global__ __launch_bounds__(THREADS, 4) void adstft_kernel(
    const float* __restrict__ x,
    const float* __restrict__ win_length,
    const float* __restrict__ strides,
    float* __restrict__ out)
{
    __shared__ float h_sm[TT][HSTRIDE];  // folded frames: [0..255] even-f, [260..515] odd-f
    __shared__ float frac_sm[TT];

    const int tid = threadIdx.x;
    const int t0  = blockIdx.x * TT;
    const int b   = blockIdx.y;

    // runtime params (clipped as in reference)
    float wl = win_length[0];
    wl = fminf(fmaxf(wl, 25.6f), 512.0f);          // WIN_MIN = N/20, WIN_MAX = N
    float st = strides[0];
    st = fminf(fmaxf(st, 0.0f), 512.0f);           // STRIDE_MIN=0, STRIDE_MAX=max(N,STRIDE)

    const float hi      = ceilf((511.0f + wl) * 0.5f);   // ceil((N-1+wl)/2)
    const float lo      = floorf((511.0f - wl) * 0.5f);  // floor((N-1-wl)/2)
    const float coff    = (wl - 511.0f) * 0.5f;          // (wl - N + 1)/2
    const float inv_wl2 = 2.0f / wl;                     // cos(2*pi*y/wl) = cospif(2y/wl)

    // Window + radix-2 fold fused: for n in [0,256):
    //   h_even[n] = g(n) + g(n+256), h_odd[n] = g(n) - g(n+256)
    for (int tt = 0; tt < TT; ++tt) {
        const int t = t0 + tt;
        const float frames = st * (float)t;
        const float fl     = floorf(frames);
        const float frac   = frames - fl;
        const int   i0     = (int)fl;
        if (tid == 0) frac_sm[tt] = frac;
        const bool tv = (t < Tc);
        for (int n = tid; n < 256; n += THREADS) {
            float v0 = 0.0f, v1 = 0.0f;
            if (tv) {
                const float base0 = (float)n - frac;
                if (base0 > lo && base0 < hi) {
                    const float tap = 0.5f - 0.5f * cospif((base0 + coff) * inv_wl2);
                    const int i = i0 + n;
                    if (i >= 0 && i < Lc) v0 = x[b * Lc + i] * tap * (1.0f / 256.0f);
                }
                const float base1 = (float)(n + 256) - frac;
                if (base1 > lo && base1 < hi) {
                    const float tap = 0.5f - 0.5f * cospif((base1 + coff) * inv_wl2);
                    const int i = i0 + n + 256;
                    if (i >= 0 && i < Lc) v1 = x[b * Lc + i] * tap * (1.0f / 256.0f);
                }
            }
            h_sm[tt][n]        = v0 + v1;
            h_sm[tt][HODD + n] = v0 - v1;
        }
    }
    __syncthreads();

    const int f = tid;
    if (f >= Fc) return;   // 257 active lanes; no further barriers below

    const int po = (f & 1) ? HODD : 0;   // parity-selected folded region

    // Twiddle recurrence: 4 chains w_j = e^{-2pi i f (4m+j)/512}, stepped by
    // w4 = e^{-2pi i f/128}. sincospif(a) = (sin(pi a), cos(pi a)).
    float s0, c0;
    const float fof = (float)f;
    float wre[4], wim[4];
    wre[0] = 1.0f; wim[0] = 0.0f;
    sincospif(fof * (1.0f / 256.0f), &s0, &c0); wre[1] = c0; wim[1] = -s0;
    sincospif(fof * (1.0f / 128.0f), &s0, &c0); wre[2] = c0; wim[2] = -s0;
    sincospif(fof * (3.0f / 256.0f), &s0, &c0); wre[3] = c0; wim[3] = -s0;
    float c4, ms4;
    sincospif(fof * (1.0f / 64.0f), &s0, &c4); ms4 = -s0;   // w4 = (c4, ms4)

    float re[TT], im[TT];
#pragma unroll
    for (int tt = 0; tt < TT; ++tt) { re[tt] = 0.0f; im[tt] = 0.0f; }

    // Folded DFT: 64 groups of 4 n. h via conflict-free dual-broadcast LDS.128.
    for (int n = 0; n < 256; n += 4) {
#pragma unroll
        for (int tt = 0; tt < TT; ++tt) {
            const float4 g = *(const float4*)&h_sm[tt][po + n];
            re[tt] = fmaf(g.x, wre[0], re[tt]); im[tt] = fmaf(g.x, wim[0], im[tt]);
            re[tt] = fmaf(g.y, wre[1], re[tt]); im[tt] = fmaf(g.y, wim[1], im[tt]);
            re[tt] = fmaf(g.z, wre[2], re[tt]); im[tt] = fmaf(g.z, wim[2], im[tt]);
            re[tt] = fmaf(g.w, wre[3], re[tt]); im[tt] = fmaf(g.w, wim[3], im[tt]);
        }
        // advance all 4 chains by w4
#pragma unroll
        for (int j = 0; j < 4; ++j) {
            const float r = wre[j], i = wim[j];
            wre[j] = r * c4 - i * ms4;
            wim[j] = fmaf(r, ms4, i * c4);
        }
    }

    // Fractional shift + magnitude + store (PLANAR complex layout)
#pragma unroll
    for (int tt = 0; tt < TT; ++tt) {
        const int t = t0 + tt;
        if (t >= Tc) break;
        const float ang = frac_sm[tt] * fof * (1.0f / 256.0f);  // shift = exp(+i*pi*ang)
        float ss, cc;
        sincospif(ang, &ss, &cc);
        const float r2 = re[tt] * cc - im[tt] * ss;
        const float i2 = re[tt] * ss + im[tt] * cc;
        const float spec = sqrtf(r2 * r2 + i2 * i2) + 1.1920928955078125e-7f;
        const int o1 = (b * Fc + f) * Tc + t;
        out[o1]           = spec;
        out[BFT + o1]     = r2;   // real plane
        out[2 * BFT + o1] = i2;   // imag plane
    }
}

extern "C" void kernel_launch(void* const* d_in, const int* in_sizes, int n_in,
                              void* d_out, int out_size) {
    const float* x  = (const float*)d_in[0];
    const float* wl = (const float*)d_in[1];
    const float* st = (const float*)d_in[2];
    dim3 grid((Tc + TT - 1) / TT, Bc);
    adstft_kernel<<<grid, THREADS>>>(x, wl, st, (float*)d_out);
}